// round 15
// baseline (speedup 1.0000x reference)
#include <cuda_runtime.h>
#include <cuda_fp16.h>
#include <cstdint>

// NormAttention, sm_103 legacy mma.sync path. R15 = R7/R14 attn core with ONE
// change: masking applied post-pack as BFE.S32+PRMT+LOP3 per fp16x2 pair
// (bit-identical to SELP+pack; masked lanes = 0xF0E2 = fp16(-10000) exactly).
// Measured identical-code variance is ~±7% (102.4-118.9us) — only mechanical
// instruction cuts with zero reg-pressure risk are issued from here.

namespace {
constexpr int Ldim = 2048, Dd = 64, BM = 128, BN = 64, NT = Ldim / BN;  // NT=32
constexpr int KB0 = 4096, VB0 = 8192, SMEMW = 12288;   // 49152 B
constexpr int OSTR = 68;
constexpr uint32_t NEGPK = 0xF0E2F0E2u;                // (-10000,-10000) fp16x2

__device__ __forceinline__ uint32_t pk2(float x, float y) {
    __half2 h = __floats2half2_rn(x, y);
    return *reinterpret_cast<uint32_t*>(&h);
}
__device__ __forceinline__ void mma16(float c[4], const uint32_t a[4], const uint32_t b[2]) {
    asm volatile(
        "mma.sync.aligned.m16n8k16.row.col.f32.f16.f16.f32 "
        "{%0,%1,%2,%3},{%4,%5,%6,%7},{%8,%9},{%0,%1,%2,%3};"
        : "+f"(c[0]), "+f"(c[1]), "+f"(c[2]), "+f"(c[3])
        : "r"(a[0]), "r"(a[1]), "r"(a[2]), "r"(a[3]), "r"(b[0]), "r"(b[1]));
}
__device__ __forceinline__ void ldsm4(uint32_t r[4], uint32_t addr) {
    asm volatile("ldmatrix.sync.aligned.m8n8.x4.shared.b16 {%0,%1,%2,%3},[%4];"
        : "=r"(r[0]), "=r"(r[1]), "=r"(r[2]), "=r"(r[3]) : "r"(addr));
}
__device__ __forceinline__ void cpa16(uint32_t s, const void* g) {
    asm volatile("cp.async.cg.shared.global [%0],[%1],16;" :: "r"(s), "l"(g));
}
__device__ __forceinline__ void cp_commit() { asm volatile("cp.async.commit_group;"); }
__device__ __forceinline__ void cp_wait0()  { asm volatile("cp.async.wait_group 0;"); }
__device__ __forceinline__ uint32_t bfes(uint32_t x, int pos) {
    int r; asm("bfe.s32 %0,%1,%2,1;" : "=r"(r) : "r"(x), "r"(pos));
    return (uint32_t)r;
}
__device__ __forceinline__ uint32_t maskpk(uint32_t pk, uint32_t m, int pos) {
    uint32_t sel = __byte_perm(bfes(m, pos), bfes(m, pos + 1), 0x7610);
    return (pk & sel) | (NEGPK & ~sel);   // one LOP3 after sel build
}
} // namespace

// static device scratch
__device__ __align__(16) uint32_t g_kh[24 * Ldim * 32];   // K packed fp16x2 [row][32w]
__device__ __align__(16) uint32_t g_vh[24 * Ldim * 32];   // V^T per 64-tile [bh][kt][n][32w]
__device__ __align__(16) uint32_t g_mb[Ldim * 64];        // mask bits [row][64 words]

__global__ void cvt_k_k(const float* __restrict__ K, int total) {
    int idx = blockIdx.x * blockDim.x + threadIdx.x;
    if (idx >= total) return;
    float2 t = *(const float2*)(K + 2 * (size_t)idx);
    g_kh[idx] = pk2(t.x, t.y);
}
__global__ void cvt_v_k(const float* __restrict__ V) {
    __shared__ float t[64][65];
    const int kt = blockIdx.x, bh = blockIdx.y, tid = threadIdx.x;
    const float* vp = V + (size_t)bh * Ldim * Dd + (size_t)kt * 64 * Dd;
    #pragma unroll
    for (int i = 0; i < 16; ++i) {
        int idx = tid + i * 256;
        t[idx >> 6][idx & 63] = vp[idx];
    }
    __syncthreads();
    uint32_t* dst = g_vh + (size_t)(bh * NT + kt) * 64 * 32;
    #pragma unroll
    for (int i = 0; i < 8; ++i) {
        int idx = tid + i * 256, n = idx >> 5, p = idx & 31;
        dst[n * 32 + p] = pk2(t[2 * p][n], t[2 * p + 1][n]);
    }
}
// 8x parallel mask packing: one warp per (row, 8-word chunk)
__global__ void pack_mask_k(const int* __restrict__ mask) {
    int wid = (blockIdx.x * blockDim.x + threadIdx.x) >> 5;
    int l = threadIdx.x & 31;
    if (wid >= Ldim * 8) return;
    int row = wid >> 3, ck = wid & 7;
    const int* mr = mask + (size_t)row * Ldim + ck * 256;
    uint32_t* orow = g_mb + (size_t)row * 64 + ck * 8;
    #pragma unroll
    for (int i = 0; i < 8; ++i) {
        uint32_t b = __ballot_sync(0xFFFFFFFFu, mr[i * 32 + l] != 0);
        if (l == 0) orow[i] = b;
    }
}

__global__ __launch_bounds__(256, 2)
void attn_k(const float* __restrict__ Q,
            const float* __restrict__ gamma, const float* __restrict__ beta,
            float* __restrict__ out)
{
    extern __shared__ uint32_t sm32[];
    const int tid = threadIdx.x, warp = tid >> 5, lane = tid & 31;
    const int g = lane >> 2, tg = lane & 3;
    const int wm = warp >> 1, wn = warp & 1;      // 4x2 warp grid
    const int row0 = wm * 32, col0 = wn * 32;     // 32 rows, 32-wide k-slice
    const int qt = blockIdx.x, bh = blockIdx.y;
    const size_t bho = (size_t)bh * Ldim * Dd;
    const uint32_t sb = (uint32_t)__cvta_generic_to_shared(sm32);

    // ldmatrix per-lane geometry (128B rows, phase = lane&7)
    const int l7 = lane & 7;
    const int csA = lane >> 4;
    const int rA8 = ((lane >> 3) & 1) * 8 + l7;
    const int csB = (lane >> 3) & 1;
    const int rB8 = ((lane >> 4) & 1) * 8 + l7;
    const uint32_t qb0 = sb + (uint32_t)(row0 + rA8) * 128;
    const uint32_t qb1 = qb0 + 16 * 128;
    const uint32_t kb0 = (uint32_t)(col0 + rB8) * 128;
    const uint32_t vb_ = (uint32_t)rB8 * 128;

    const int gq0 = qt * BM + row0 + g;

    // ---- stage Q packed fp16x2 (swizzled chunks) ----
    const float* qp = Q + bho + (size_t)qt * BM * Dd;
    #pragma unroll
    for (int j = 0; j < 8; ++j) {
        int i = tid + j * 256, r = i >> 4, h = i & 15;
        float4 t = *(const float4*)(qp + (size_t)r * Dd + 4 * h);
        int c = h >> 1, w = (h & 1) * 2;
        *(uint2*)(sm32 + r * 32 + ((c ^ (r & 7)) << 2) + w) =
            make_uint2(pk2(t.x, t.y), pk2(t.z, t.w));
    }
    // ---- prefetch tile 0 ----
    {
        const uint32_t* kg = g_kh + (size_t)bh * Ldim * 32;
        const uint32_t* vg = g_vh + (size_t)bh * Ldim * 32;
        #pragma unroll
        for (int j = 0; j < 4; ++j) {
            int ch = tid + j * 256;
            int r = (ch & 511) >> 3, c = ch & 7;
            const uint32_t* src = (ch < 512 ? kg : vg) + r * 32 + c * 4;
            int base = (ch < 512 ? KB0 : VB0);
            cpa16(sb + (uint32_t)(base + r * 32 + ((c ^ (r & 7)) << 2)) * 4u, src);
        }
        cp_commit();
    }

    float o[2][8][4] = {};   // partial O 32x64 over this warp's 32-wide k-slice

    for (int kt = 0; kt < NT; ++kt) {
        const int buf = kt & 1;
        cp_wait0();
        __syncthreads();

        // mask words (4 LDG.32, independent — hide under GEMM1)
        const uint32_t mr00 = g_mb[(size_t)gq0 * 64 + kt * 2 + wn];
        const uint32_t mr01 = g_mb[(size_t)(gq0 + 8) * 64 + kt * 2 + wn];
        const uint32_t mr10 = g_mb[(size_t)(gq0 + 16) * 64 + kt * 2 + wn];
        const uint32_t mr11 = g_mb[(size_t)(gq0 + 24) * 64 + kt * 2 + wn];

        if (kt + 1 < NT) {
            const uint32_t* kg = g_kh + ((size_t)bh * Ldim + (kt + 1) * 64) * 32;
            const uint32_t* vg = g_vh + ((size_t)bh * NT + kt + 1) * 64 * 32;
            const int bo = (buf ^ 1) * 2048;
            #pragma unroll
            for (int j = 0; j < 4; ++j) {
                int ch = tid + j * 256;
                int r = (ch & 511) >> 3, c = ch & 7;
                const uint32_t* src = (ch < 512 ? kg : vg) + r * 32 + c * 4;
                int base = (ch < 512 ? KB0 : VB0) + bo;
                cpa16(sb + (uint32_t)(base + r * 32 + ((c ^ (r & 7)) << 2)) * 4u, src);
            }
            cp_commit();
        }

        const uint32_t kbuf = sb + (uint32_t)(KB0 + buf * 2048) * 4u;
        const uint32_t vbuf = sb + (uint32_t)(VB0 + buf * 2048) * 4u;

        // ---- GEMM1: S(32x32) = Q @ K^T over D=64 ----
        float s[2][4][4] = {};
        #pragma unroll
        for (int m = 0; m < 4; ++m) {
            const uint32_t cxa = (uint32_t)(((2 * m + csA) ^ l7) << 4);
            const uint32_t cxb = (uint32_t)(((2 * m + csB) ^ l7) << 4);
            uint32_t a0[4], a1[4], b0[4], b1[4];
            ldsm4(a0, qb0 + cxa);
            ldsm4(a1, qb1 + cxa);
            ldsm4(b0, kbuf + kb0 + cxb);
            ldsm4(b1, kbuf + kb0 + 16 * 128 + cxb);
            mma16(s[0][0], a0, b0);     mma16(s[0][1], a0, b0 + 2);
            mma16(s[0][2], a0, b1);     mma16(s[0][3], a0, b1 + 2);
            mma16(s[1][0], a1, b0);     mma16(s[1][1], a1, b0 + 2);
            mma16(s[1][2], a1, b1);     mma16(s[1][3], a1, b1 + 2);
        }

        // ---- pack, then mask packed pairs: BFE+PRMT+LOP3 (bit-identical) ----
        uint32_t sp[2][4][2];
        #pragma unroll
        for (int mi = 0; mi < 2; ++mi) {
            const uint32_t m0 = mi ? mr10 : mr00;
            const uint32_t m1 = mi ? mr11 : mr01;
            #pragma unroll
            for (int nj = 0; nj < 4; ++nj) {
                const int pos = nj * 8 + 2 * tg;
                sp[mi][nj][0] = maskpk(pk2(s[mi][nj][0], s[mi][nj][1]), m0, pos);
                sp[mi][nj][1] = maskpk(pk2(s[mi][nj][2], s[mi][nj][3]), m1, pos);
            }
        }

        // ---- GEMM2: O_partial(32x64) += S_slice(32) @ V ----
        #pragma unroll
        for (int ks = 0; ks < 2; ++ks) {
            uint32_t a0[4] = { sp[0][2*ks][0], sp[0][2*ks][1],
                               sp[0][2*ks+1][0], sp[0][2*ks+1][1] };
            uint32_t a1[4] = { sp[1][2*ks][0], sp[1][2*ks][1],
                               sp[1][2*ks+1][0], sp[1][2*ks+1][1] };
            const uint32_t cx = (uint32_t)((((4 * wn + 2 * ks) + csB) ^ l7) << 4);
            #pragma unroll
            for (int njp = 0; njp < 4; ++njp) {
                uint32_t bv[4];
                ldsm4(bv, vbuf + vb_ + (uint32_t)njp * (16 * 128) + cx);
                mma16(o[0][2*njp],   a0, bv);     mma16(o[0][2*njp+1], a0, bv + 2);
                mma16(o[1][2*njp],   a1, bv);     mma16(o[1][2*njp+1], a1, bv + 2);
            }
        }
    }

    // ---- reduce partial O across the 2 wn-warps ----
    float* smf = reinterpret_cast<float*>(sm32);
    __syncthreads();
    #pragma unroll
    for (int w = 0; w < 2; ++w) {
        if (wn == w) {
            #pragma unroll
            for (int mi = 0; mi < 2; ++mi) {
                #pragma unroll
                for (int nj = 0; nj < 8; ++nj) {
                    const int rl = row0 + mi * 16 + g;
                    const int cl = nj * 8 + 2 * tg;
                    float* p0 = smf + rl * OSTR + cl;
                    float* p1 = smf + (rl + 8) * OSTR + cl;
                    if (w == 0) {
                        *(float2*)p0 = make_float2(o[mi][nj][0], o[mi][nj][1]);
                        *(float2*)p1 = make_float2(o[mi][nj][2], o[mi][nj][3]);
                    } else {
                        float2 t0 = *(float2*)p0, t1 = *(float2*)p1;
                        t0.x += o[mi][nj][0]; t0.y += o[mi][nj][1];
                        t1.x += o[mi][nj][2]; t1.y += o[mi][nj][3];
                        *(float2*)p0 = t0;
                        *(float2*)p1 = t1;
                    }
                }
            }
        }
        __syncthreads();
    }

    // ---- LayerNorm over D=64 ----
    if (tid < BM) {
        const float* rowp = smf + tid * OSTR;
        float x[Dd]; float sum = 0.0f;
        #pragma unroll
        for (int c = 0; c < Dd; c += 4) {
            float4 t = *(const float4*)(rowp + c);
            x[c] = t.x; x[c+1] = t.y; x[c+2] = t.z; x[c+3] = t.w;
            sum += t.x + t.y + t.z + t.w;
        }
        const float mean = sum * (1.0f / Dd);
        float var = 0.0f;
        #pragma unroll
        for (int c = 0; c < Dd; ++c) { float d = x[c] - mean; var += d * d; }
        const float inv = rsqrtf(var * (1.0f / Dd) + 1e-12f);
        float* op = out + bho + (size_t)(qt * BM + tid) * Dd;
        #pragma unroll
        for (int c = 0; c < Dd; c += 4) {
            float4 t = make_float4(
                (x[c]   - mean) * inv * __ldg(gamma + c)     + __ldg(beta + c),
                (x[c+1] - mean) * inv * __ldg(gamma + c + 1) + __ldg(beta + c + 1),
                (x[c+2] - mean) * inv * __ldg(gamma + c + 2) + __ldg(beta + c + 2),
                (x[c+3] - mean) * inv * __ldg(gamma + c + 3) + __ldg(beta + c + 3));
            *(float4*)(op + c) = t;
        }
    }
}

extern "C" void kernel_launch(void* const* d_in, const int* in_sizes, int n_in,
                              void* d_out, int out_size)
{
    const float* q     = (const float*)d_in[0];
    const float* k     = (const float*)d_in[1];
    const float* v     = (const float*)d_in[2];
    const int*   mask  = (const int*)  d_in[3];
    const float* gamma = (const float*)d_in[4];
    const float* beta  = (const float*)d_in[5];
    float* out = (float*)d_out;

    const int bh = in_sizes[0] / (Ldim * Dd);   // 24
    const int ktotal = bh * Ldim * 32;

    cvt_k_k<<<(ktotal + 255) / 256, 256>>>(k, ktotal);
    cvt_v_k<<<dim3(NT, bh), 256>>>(v);
    pack_mask_k<<<Ldim * 8 * 32 / 256, 256>>>(mask);

    cudaFuncSetAttribute(attn_k, cudaFuncAttributeMaxDynamicSharedMemorySize,
                         SMEMW * (int)sizeof(uint32_t));
    attn_k<<<dim3(Ldim / BM, bh), 256, SMEMW * (int)sizeof(uint32_t)>>>(
        q, gamma, beta, out);
}

// round 16
// speedup vs baseline: 1.0312x; 1.0312x over previous
#include <cuda_runtime.h>
#include <cuda_fp16.h>
#include <cstdint>

// NormAttention, sm_103 legacy mma.sync path. R16 = best-known configuration,
// re-benched: R7 attn core VERBATIM (fp16 m16n8k16 fp32-accum, ldmatrix.x4
// XOR-swizzled smem, S-in-registers, SELP mask, 256 thr / 2 CTA/SM, depth-1
// cp.async double buffer) + 8x-parallel mask packing. Identical-SASS variance
// measured at ±8% @NAT; all structural variants (R8-R15) landed above band.

namespace {
constexpr int Ldim = 2048, Dd = 64, BM = 128, BN = 64, NT = Ldim / BN;  // NT=32
constexpr int KB0 = 4096, VB0 = 8192, SMEMW = 12288;   // 49152 B
constexpr int OSTR = 68;

__device__ __forceinline__ uint32_t pk2(float x, float y) {
    __half2 h = __floats2half2_rn(x, y);
    return *reinterpret_cast<uint32_t*>(&h);
}
__device__ __forceinline__ void mma16(float c[4], const uint32_t a[4], const uint32_t b[2]) {
    asm volatile(
        "mma.sync.aligned.m16n8k16.row.col.f32.f16.f16.f32 "
        "{%0,%1,%2,%3},{%4,%5,%6,%7},{%8,%9},{%0,%1,%2,%3};"
        : "+f"(c[0]), "+f"(c[1]), "+f"(c[2]), "+f"(c[3])
        : "r"(a[0]), "r"(a[1]), "r"(a[2]), "r"(a[3]), "r"(b[0]), "r"(b[1]));
}
__device__ __forceinline__ void ldsm4(uint32_t r[4], uint32_t addr) {
    asm volatile("ldmatrix.sync.aligned.m8n8.x4.shared.b16 {%0,%1,%2,%3},[%4];"
        : "=r"(r[0]), "=r"(r[1]), "=r"(r[2]), "=r"(r[3]) : "r"(addr));
}
__device__ __forceinline__ void cpa16(uint32_t s, const void* g) {
    asm volatile("cp.async.cg.shared.global [%0],[%1],16;" :: "r"(s), "l"(g));
}
__device__ __forceinline__ void cp_commit() { asm volatile("cp.async.commit_group;"); }
__device__ __forceinline__ void cp_wait0()  { asm volatile("cp.async.wait_group 0;"); }
} // namespace

// static device scratch
__device__ __align__(16) uint32_t g_kh[24 * Ldim * 32];   // K packed fp16x2 [row][32w]
__device__ __align__(16) uint32_t g_vh[24 * Ldim * 32];   // V^T per 64-tile [bh][kt][n][32w]
__device__ __align__(16) uint32_t g_mb[Ldim * 64];        // mask bits [row][64 words]

__global__ void cvt_k_k(const float* __restrict__ K, int total) {
    int idx = blockIdx.x * blockDim.x + threadIdx.x;
    if (idx >= total) return;
    float2 t = *(const float2*)(K + 2 * (size_t)idx);
    g_kh[idx] = pk2(t.x, t.y);
}
__global__ void cvt_v_k(const float* __restrict__ V) {
    __shared__ float t[64][65];
    const int kt = blockIdx.x, bh = blockIdx.y, tid = threadIdx.x;
    const float* vp = V + (size_t)bh * Ldim * Dd + (size_t)kt * 64 * Dd;
    #pragma unroll
    for (int i = 0; i < 16; ++i) {
        int idx = tid + i * 256;
        t[idx >> 6][idx & 63] = vp[idx];
    }
    __syncthreads();
    uint32_t* dst = g_vh + (size_t)(bh * NT + kt) * 64 * 32;
    #pragma unroll
    for (int i = 0; i < 8; ++i) {
        int idx = tid + i * 256, n = idx >> 5, p = idx & 31;
        dst[n * 32 + p] = pk2(t[2 * p][n], t[2 * p + 1][n]);
    }
}
// 8x parallel mask packing: one warp per (row, 8-word chunk)
__global__ void pack_mask_k(const int* __restrict__ mask) {
    int wid = (blockIdx.x * blockDim.x + threadIdx.x) >> 5;
    int l = threadIdx.x & 31;
    if (wid >= Ldim * 8) return;
    int row = wid >> 3, ck = wid & 7;
    const int* mr = mask + (size_t)row * Ldim + ck * 256;
    uint32_t* orow = g_mb + (size_t)row * 64 + ck * 8;
    #pragma unroll
    for (int i = 0; i < 8; ++i) {
        uint32_t b = __ballot_sync(0xFFFFFFFFu, mr[i * 32 + l] != 0);
        if (l == 0) orow[i] = b;
    }
}

__global__ __launch_bounds__(256, 2)
void attn_k(const float* __restrict__ Q,
            const float* __restrict__ gamma, const float* __restrict__ beta,
            float* __restrict__ out)
{
    extern __shared__ uint32_t sm32[];
    const int tid = threadIdx.x, warp = tid >> 5, lane = tid & 31;
    const int g = lane >> 2, tg = lane & 3;
    const int wm = warp >> 1, wn = warp & 1;      // 4x2 warp grid
    const int row0 = wm * 32, col0 = wn * 32;     // 32 rows, 32-wide k-slice
    const int qt = blockIdx.x, bh = blockIdx.y;
    const size_t bho = (size_t)bh * Ldim * Dd;
    const uint32_t sb = (uint32_t)__cvta_generic_to_shared(sm32);

    // ldmatrix per-lane geometry (128B rows, phase = lane&7)
    const int l7 = lane & 7;
    const int csA = lane >> 4;
    const int rA8 = ((lane >> 3) & 1) * 8 + l7;
    const int csB = (lane >> 3) & 1;
    const int rB8 = ((lane >> 4) & 1) * 8 + l7;
    const uint32_t qb0 = sb + (uint32_t)(row0 + rA8) * 128;
    const uint32_t qb1 = qb0 + 16 * 128;
    const uint32_t kb0 = (uint32_t)(col0 + rB8) * 128;
    const uint32_t vb_ = (uint32_t)rB8 * 128;

    // mask geometry: this warp covers cols [kt*64 + wn*32, +32)
    const int gq0 = qt * BM + row0 + g;

    // ---- stage Q packed fp16x2 (swizzled chunks) ----
    const float* qp = Q + bho + (size_t)qt * BM * Dd;
    #pragma unroll
    for (int j = 0; j < 8; ++j) {
        int i = tid + j * 256, r = i >> 4, h = i & 15;
        float4 t = *(const float4*)(qp + (size_t)r * Dd + 4 * h);
        int c = h >> 1, w = (h & 1) * 2;
        *(uint2*)(sm32 + r * 32 + ((c ^ (r & 7)) << 2) + w) =
            make_uint2(pk2(t.x, t.y), pk2(t.z, t.w));
    }
    // ---- prefetch tile 0 ----
    {
        const uint32_t* kg = g_kh + (size_t)bh * Ldim * 32;
        const uint32_t* vg = g_vh + (size_t)bh * Ldim * 32;
        #pragma unroll
        for (int j = 0; j < 4; ++j) {
            int ch = tid + j * 256;
            int r = (ch & 511) >> 3, c = ch & 7;
            const uint32_t* src = (ch < 512 ? kg : vg) + r * 32 + c * 4;
            int base = (ch < 512 ? KB0 : VB0);
            cpa16(sb + (uint32_t)(base + r * 32 + ((c ^ (r & 7)) << 2)) * 4u, src);
        }
        cp_commit();
    }

    float o[2][8][4] = {};   // partial O 32x64 over this warp's 32-wide k-slice

    for (int kt = 0; kt < NT; ++kt) {
        const int buf = kt & 1;
        cp_wait0();
        __syncthreads();

        // mask words (4 LDG.32, independent — hide under GEMM1)
        const uint32_t mr00 = g_mb[(size_t)gq0 * 64 + kt * 2 + wn];
        const uint32_t mr01 = g_mb[(size_t)(gq0 + 8) * 64 + kt * 2 + wn];
        const uint32_t mr10 = g_mb[(size_t)(gq0 + 16) * 64 + kt * 2 + wn];
        const uint32_t mr11 = g_mb[(size_t)(gq0 + 24) * 64 + kt * 2 + wn];

        if (kt + 1 < NT) {
            const uint32_t* kg = g_kh + ((size_t)bh * Ldim + (kt + 1) * 64) * 32;
            const uint32_t* vg = g_vh + ((size_t)bh * NT + kt + 1) * 64 * 32;
            const int bo = (buf ^ 1) * 2048;
            #pragma unroll
            for (int j = 0; j < 4; ++j) {
                int ch = tid + j * 256;
                int r = (ch & 511) >> 3, c = ch & 7;
                const uint32_t* src = (ch < 512 ? kg : vg) + r * 32 + c * 4;
                int base = (ch < 512 ? KB0 : VB0) + bo;
                cpa16(sb + (uint32_t)(base + r * 32 + ((c ^ (r & 7)) << 2)) * 4u, src);
            }
            cp_commit();
        }

        const uint32_t kbuf = sb + (uint32_t)(KB0 + buf * 2048) * 4u;
        const uint32_t vbuf = sb + (uint32_t)(VB0 + buf * 2048) * 4u;

        // ---- GEMM1: S(32x32) = Q @ K^T over D=64 ----
        float s[2][4][4] = {};
        #pragma unroll
        for (int m = 0; m < 4; ++m) {
            const uint32_t cxa = (uint32_t)(((2 * m + csA) ^ l7) << 4);
            const uint32_t cxb = (uint32_t)(((2 * m + csB) ^ l7) << 4);
            uint32_t a0[4], a1[4], b0[4], b1[4];
            ldsm4(a0, qb0 + cxa);
            ldsm4(a1, qb1 + cxa);
            ldsm4(b0, kbuf + kb0 + cxb);
            ldsm4(b1, kbuf + kb0 + 16 * 128 + cxb);
            mma16(s[0][0], a0, b0);     mma16(s[0][1], a0, b0 + 2);
            mma16(s[0][2], a0, b1);     mma16(s[0][3], a0, b1 + 2);
            mma16(s[1][0], a1, b0);     mma16(s[1][1], a1, b0 + 2);
            mma16(s[1][2], a1, b1);     mma16(s[1][3], a1, b1 + 2);
        }

        // ---- mask in fp32 (-1e4 exact in fp16) ----
        #pragma unroll
        for (int mi = 0; mi < 2; ++mi) {
            const uint32_t m0 = mi ? mr10 : mr00;
            const uint32_t m1 = mi ? mr11 : mr01;
            #pragma unroll
            for (int nj = 0; nj < 4; ++nj) {
                const int pos = nj * 8 + 2 * tg;
                s[mi][nj][0] = ((m0 >> pos) & 1)       ? s[mi][nj][0] : -10000.0f;
                s[mi][nj][1] = ((m0 >> (pos + 1)) & 1) ? s[mi][nj][1] : -10000.0f;
                s[mi][nj][2] = ((m1 >> pos) & 1)       ? s[mi][nj][2] : -10000.0f;
                s[mi][nj][3] = ((m1 >> (pos + 1)) & 1) ? s[mi][nj][3] : -10000.0f;
            }
        }

        // ---- pack -> GEMM2 A-frags ----
        uint32_t sp[2][4][2];
        #pragma unroll
        for (int mi = 0; mi < 2; ++mi)
            #pragma unroll
            for (int nj = 0; nj < 4; ++nj) {
                sp[mi][nj][0] = pk2(s[mi][nj][0], s[mi][nj][1]);
                sp[mi][nj][1] = pk2(s[mi][nj][2], s[mi][nj][3]);
            }

        // ---- GEMM2: O_partial(32x64) += S_slice(32) @ V ----
        #pragma unroll
        for (int ks = 0; ks < 2; ++ks) {
            uint32_t a0[4] = { sp[0][2*ks][0], sp[0][2*ks][1],
                               sp[0][2*ks+1][0], sp[0][2*ks+1][1] };
            uint32_t a1[4] = { sp[1][2*ks][0], sp[1][2*ks][1],
                               sp[1][2*ks+1][0], sp[1][2*ks+1][1] };
            const uint32_t cx = (uint32_t)((((4 * wn + 2 * ks) + csB) ^ l7) << 4);
            #pragma unroll
            for (int njp = 0; njp < 4; ++njp) {
                uint32_t bv[4];
                ldsm4(bv, vbuf + vb_ + (uint32_t)njp * (16 * 128) + cx);
                mma16(o[0][2*njp],   a0, bv);     mma16(o[0][2*njp+1], a0, bv + 2);
                mma16(o[1][2*njp],   a1, bv);     mma16(o[1][2*njp+1], a1, bv + 2);
            }
        }
    }

    // ---- reduce partial O across the 2 wn-warps ----
    float* smf = reinterpret_cast<float*>(sm32);
    __syncthreads();
    #pragma unroll
    for (int w = 0; w < 2; ++w) {
        if (wn == w) {
            #pragma unroll
            for (int mi = 0; mi < 2; ++mi) {
                #pragma unroll
                for (int nj = 0; nj < 8; ++nj) {
                    const int rl = row0 + mi * 16 + g;
                    const int cl = nj * 8 + 2 * tg;
                    float* p0 = smf + rl * OSTR + cl;
                    float* p1 = smf + (rl + 8) * OSTR + cl;
                    if (w == 0) {
                        *(float2*)p0 = make_float2(o[mi][nj][0], o[mi][nj][1]);
                        *(float2*)p1 = make_float2(o[mi][nj][2], o[mi][nj][3]);
                    } else {
                        float2 t0 = *(float2*)p0, t1 = *(float2*)p1;
                        t0.x += o[mi][nj][0]; t0.y += o[mi][nj][1];
                        t1.x += o[mi][nj][2]; t1.y += o[mi][nj][3];
                        *(float2*)p0 = t0;
                        *(float2*)p1 = t1;
                    }
                }
            }
        }
        __syncthreads();
    }

    // ---- LayerNorm over D=64 ----
    if (tid < BM) {
        const float* rowp = smf + tid * OSTR;
        float x[Dd]; float sum = 0.0f;
        #pragma unroll
        for (int c = 0; c < Dd; c += 4) {
            float4 t = *(const float4*)(rowp + c);
            x[c] = t.x; x[c+1] = t.y; x[c+2] = t.z; x[c+3] = t.w;
            sum += t.x + t.y + t.z + t.w;
        }
        const float mean = sum * (1.0f / Dd);
        float var = 0.0f;
        #pragma unroll
        for (int c = 0; c < Dd; ++c) { float d = x[c] - mean; var += d * d; }
        const float inv = rsqrtf(var * (1.0f / Dd) + 1e-12f);
        float* op = out + bho + (size_t)(qt * BM + tid) * Dd;
        #pragma unroll
        for (int c = 0; c < Dd; c += 4) {
            float4 t = make_float4(
                (x[c]   - mean) * inv * __ldg(gamma + c)     + __ldg(beta + c),
                (x[c+1] - mean) * inv * __ldg(gamma + c + 1) + __ldg(beta + c + 1),
                (x[c+2] - mean) * inv * __ldg(gamma + c + 2) + __ldg(beta + c + 2),
                (x[c+3] - mean) * inv * __ldg(gamma + c + 3) + __ldg(beta + c + 3));
            *(float4*)(op + c) = t;
        }
    }
}

extern "C" void kernel_launch(void* const* d_in, const int* in_sizes, int n_in,
                              void* d_out, int out_size)
{
    const float* q     = (const float*)d_in[0];
    const float* k     = (const float*)d_in[1];
    const float* v     = (const float*)d_in[2];
    const int*   mask  = (const int*)  d_in[3];
    const float* gamma = (const float*)d_in[4];
    const float* beta  = (const float*)d_in[5];
    float* out = (float*)d_out;

    const int bh = in_sizes[0] / (Ldim * Dd);   // 24
    const int ktotal = bh * Ldim * 32;

    cvt_k_k<<<(ktotal + 255) / 256, 256>>>(k, ktotal);
    cvt_v_k<<<dim3(NT, bh), 256>>>(v);
    pack_mask_k<<<Ldim * 8 * 32 / 256, 256>>>(mask);

    cudaFuncSetAttribute(attn_k, cudaFuncAttributeMaxDynamicSharedMemorySize,
                         SMEMW * (int)sizeof(uint32_t));
    attn_k<<<dim3(Ldim / BM, bh), 256, SMEMW * (int)sizeof(uint32_t)>>>(
        q, gamma, beta, out);
}

// round 17
// speedup vs baseline: 1.0563x; 1.0243x over previous
#include <cuda_runtime.h>
#include <cuda_fp16.h>
#include <cstdint>

// NormAttention, sm_103 legacy mma.sync path. R17 = R7/R16 attn core VERBATIM
// (fp16 m16n8k16 fp32-accum, ldmatrix.x4 XOR-swizzled smem, S-in-registers,
// SELP mask, 256 thr / 2 CTA/SM, depth-1 cp.async double buffer) + ALL THREE
// preludes fused into one launch (block-range partitioned) to cut the measured
// ~9.5us prelude/launch overhead to ~6us. attn_k steady-state is 115.7us +-
// clock noise; core edits are closed (9 variants all landed at/above band).

namespace {
constexpr int Ldim = 2048, Dd = 64, BM = 128, BN = 64, NT = Ldim / BN;  // NT=32
constexpr int KB0 = 4096, VB0 = 8192, SMEMW = 12288;   // 49152 B
constexpr int OSTR = 68;

__device__ __forceinline__ uint32_t pk2(float x, float y) {
    __half2 h = __floats2half2_rn(x, y);
    return *reinterpret_cast<uint32_t*>(&h);
}
__device__ __forceinline__ void mma16(float c[4], const uint32_t a[4], const uint32_t b[2]) {
    asm volatile(
        "mma.sync.aligned.m16n8k16.row.col.f32.f16.f16.f32 "
        "{%0,%1,%2,%3},{%4,%5,%6,%7},{%8,%9},{%0,%1,%2,%3};"
        : "+f"(c[0]), "+f"(c[1]), "+f"(c[2]), "+f"(c[3])
        : "r"(a[0]), "r"(a[1]), "r"(a[2]), "r"(a[3]), "r"(b[0]), "r"(b[1]));
}
__device__ __forceinline__ void ldsm4(uint32_t r[4], uint32_t addr) {
    asm volatile("ldmatrix.sync.aligned.m8n8.x4.shared.b16 {%0,%1,%2,%3},[%4];"
        : "=r"(r[0]), "=r"(r[1]), "=r"(r[2]), "=r"(r[3]) : "r"(addr));
}
__device__ __forceinline__ void cpa16(uint32_t s, const void* g) {
    asm volatile("cp.async.cg.shared.global [%0],[%1],16;" :: "r"(s), "l"(g));
}
__device__ __forceinline__ void cp_commit() { asm volatile("cp.async.commit_group;"); }
__device__ __forceinline__ void cp_wait0()  { asm volatile("cp.async.wait_group 0;"); }
} // namespace

// static device scratch
__device__ __align__(16) uint32_t g_kh[24 * Ldim * 32];   // K packed fp16x2 [row][32w]
__device__ __align__(16) uint32_t g_vh[24 * Ldim * 32];   // V^T per 64-tile [bh][kt][n][32w]
__device__ __align__(16) uint32_t g_mb[Ldim * 64];        // mask bits [row][64 words]

// ---- fused prelude: cvt_k | cvt_v | pack_mask, partitioned by blockIdx.x ----
// nk = bh*256 blocks (K convert), nv = bh*32 blocks (V transpose), 2048 blocks
// (mask pack). All branches are uniform per block, so __syncthreads is safe.
__global__ void prelude_k(const float* __restrict__ K, const float* __restrict__ V,
                          const int* __restrict__ mask, int nk, int nv)
{
    __shared__ float t[64][65];
    const int bid = blockIdx.x, tid = threadIdx.x;

    if (bid < nk) {
        // K rows -> packed fp16x2
        int idx = bid * 256 + tid;                     // < bh*Ldim*32, exact
        float2 v2 = *(const float2*)(K + 2 * (size_t)idx);
        g_kh[idx] = pk2(v2.x, v2.y);
    } else if (bid < nk + nv) {
        // V 64-tile transpose -> packed fp16x2 row-pairs
        int vb = bid - nk;
        int kt = vb & 31, bhi = vb >> 5;               // NT = 32
        const float* vp = V + (size_t)bhi * Ldim * Dd + (size_t)kt * 64 * Dd;
        #pragma unroll
        for (int i = 0; i < 16; ++i) {
            int idx = tid + i * 256;
            t[idx >> 6][idx & 63] = vp[idx];
        }
        __syncthreads();
        uint32_t* dst = g_vh + (size_t)(bhi * NT + kt) * 64 * 32;
        #pragma unroll
        for (int i = 0; i < 8; ++i) {
            int idx = tid + i * 256, n = idx >> 5, p = idx & 31;
            dst[n * 32 + p] = pk2(t[2 * p][n], t[2 * p + 1][n]);
        }
    } else {
        // mask bits: one warp per (row, 8-word chunk)
        int mb = bid - nk - nv;
        int wid = mb * 8 + (tid >> 5), l = tid & 31;
        if (wid < Ldim * 8) {
            int row = wid >> 3, ck = wid & 7;
            const int* mr = mask + (size_t)row * Ldim + ck * 256;
            uint32_t* orow = g_mb + (size_t)row * 64 + ck * 8;
            #pragma unroll
            for (int i = 0; i < 8; ++i) {
                uint32_t b = __ballot_sync(0xFFFFFFFFu, mr[i * 32 + l] != 0);
                if (l == 0) orow[i] = b;
            }
        }
    }
}

__global__ __launch_bounds__(256, 2)
void attn_k(const float* __restrict__ Q,
            const float* __restrict__ gamma, const float* __restrict__ beta,
            float* __restrict__ out)
{
    extern __shared__ uint32_t sm32[];
    const int tid = threadIdx.x, warp = tid >> 5, lane = tid & 31;
    const int g = lane >> 2, tg = lane & 3;
    const int wm = warp >> 1, wn = warp & 1;      // 4x2 warp grid
    const int row0 = wm * 32, col0 = wn * 32;     // 32 rows, 32-wide k-slice
    const int qt = blockIdx.x, bh = blockIdx.y;
    const size_t bho = (size_t)bh * Ldim * Dd;
    const uint32_t sb = (uint32_t)__cvta_generic_to_shared(sm32);

    // ldmatrix per-lane geometry (128B rows, phase = lane&7)
    const int l7 = lane & 7;
    const int csA = lane >> 4;
    const int rA8 = ((lane >> 3) & 1) * 8 + l7;
    const int csB = (lane >> 3) & 1;
    const int rB8 = ((lane >> 4) & 1) * 8 + l7;
    const uint32_t qb0 = sb + (uint32_t)(row0 + rA8) * 128;
    const uint32_t qb1 = qb0 + 16 * 128;
    const uint32_t kb0 = (uint32_t)(col0 + rB8) * 128;
    const uint32_t vb_ = (uint32_t)rB8 * 128;

    // mask geometry: this warp covers cols [kt*64 + wn*32, +32)
    const int gq0 = qt * BM + row0 + g;

    // ---- stage Q packed fp16x2 (swizzled chunks) ----
    const float* qp = Q + bho + (size_t)qt * BM * Dd;
    #pragma unroll
    for (int j = 0; j < 8; ++j) {
        int i = tid + j * 256, r = i >> 4, h = i & 15;
        float4 t = *(const float4*)(qp + (size_t)r * Dd + 4 * h);
        int c = h >> 1, w = (h & 1) * 2;
        *(uint2*)(sm32 + r * 32 + ((c ^ (r & 7)) << 2) + w) =
            make_uint2(pk2(t.x, t.y), pk2(t.z, t.w));
    }
    // ---- prefetch tile 0 ----
    {
        const uint32_t* kg = g_kh + (size_t)bh * Ldim * 32;
        const uint32_t* vg = g_vh + (size_t)bh * Ldim * 32;
        #pragma unroll
        for (int j = 0; j < 4; ++j) {
            int ch = tid + j * 256;
            int r = (ch & 511) >> 3, c = ch & 7;
            const uint32_t* src = (ch < 512 ? kg : vg) + r * 32 + c * 4;
            int base = (ch < 512 ? KB0 : VB0);
            cpa16(sb + (uint32_t)(base + r * 32 + ((c ^ (r & 7)) << 2)) * 4u, src);
        }
        cp_commit();
    }

    float o[2][8][4] = {};   // partial O 32x64 over this warp's 32-wide k-slice

    for (int kt = 0; kt < NT; ++kt) {
        const int buf = kt & 1;
        cp_wait0();
        __syncthreads();

        // mask words (4 LDG.32, independent — hide under GEMM1)
        const uint32_t mr00 = g_mb[(size_t)gq0 * 64 + kt * 2 + wn];
        const uint32_t mr01 = g_mb[(size_t)(gq0 + 8) * 64 + kt * 2 + wn];
        const uint32_t mr10 = g_mb[(size_t)(gq0 + 16) * 64 + kt * 2 + wn];
        const uint32_t mr11 = g_mb[(size_t)(gq0 + 24) * 64 + kt * 2 + wn];

        if (kt + 1 < NT) {
            const uint32_t* kg = g_kh + ((size_t)bh * Ldim + (kt + 1) * 64) * 32;
            const uint32_t* vg = g_vh + ((size_t)bh * NT + kt + 1) * 64 * 32;
            const int bo = (buf ^ 1) * 2048;
            #pragma unroll
            for (int j = 0; j < 4; ++j) {
                int ch = tid + j * 256;
                int r = (ch & 511) >> 3, c = ch & 7;
                const uint32_t* src = (ch < 512 ? kg : vg) + r * 32 + c * 4;
                int base = (ch < 512 ? KB0 : VB0) + bo;
                cpa16(sb + (uint32_t)(base + r * 32 + ((c ^ (r & 7)) << 2)) * 4u, src);
            }
            cp_commit();
        }

        const uint32_t kbuf = sb + (uint32_t)(KB0 + buf * 2048) * 4u;
        const uint32_t vbuf = sb + (uint32_t)(VB0 + buf * 2048) * 4u;

        // ---- GEMM1: S(32x32) = Q @ K^T over D=64 ----
        float s[2][4][4] = {};
        #pragma unroll
        for (int m = 0; m < 4; ++m) {
            const uint32_t cxa = (uint32_t)(((2 * m + csA) ^ l7) << 4);
            const uint32_t cxb = (uint32_t)(((2 * m + csB) ^ l7) << 4);
            uint32_t a0[4], a1[4], b0[4], b1[4];
            ldsm4(a0, qb0 + cxa);
            ldsm4(a1, qb1 + cxa);
            ldsm4(b0, kbuf + kb0 + cxb);
            ldsm4(b1, kbuf + kb0 + 16 * 128 + cxb);
            mma16(s[0][0], a0, b0);     mma16(s[0][1], a0, b0 + 2);
            mma16(s[0][2], a0, b1);     mma16(s[0][3], a0, b1 + 2);
            mma16(s[1][0], a1, b0);     mma16(s[1][1], a1, b0 + 2);
            mma16(s[1][2], a1, b1);     mma16(s[1][3], a1, b1 + 2);
        }

        // ---- mask in fp32 (-1e4 exact in fp16) ----
        #pragma unroll
        for (int mi = 0; mi < 2; ++mi) {
            const uint32_t m0 = mi ? mr10 : mr00;
            const uint32_t m1 = mi ? mr11 : mr01;
            #pragma unroll
            for (int nj = 0; nj < 4; ++nj) {
                const int pos = nj * 8 + 2 * tg;
                s[mi][nj][0] = ((m0 >> pos) & 1)       ? s[mi][nj][0] : -10000.0f;
                s[mi][nj][1] = ((m0 >> (pos + 1)) & 1) ? s[mi][nj][1] : -10000.0f;
                s[mi][nj][2] = ((m1 >> pos) & 1)       ? s[mi][nj][2] : -10000.0f;
                s[mi][nj][3] = ((m1 >> (pos + 1)) & 1) ? s[mi][nj][3] : -10000.0f;
            }
        }

        // ---- pack -> GEMM2 A-frags ----
        uint32_t sp[2][4][2];
        #pragma unroll
        for (int mi = 0; mi < 2; ++mi)
            #pragma unroll
            for (int nj = 0; nj < 4; ++nj) {
                sp[mi][nj][0] = pk2(s[mi][nj][0], s[mi][nj][1]);
                sp[mi][nj][1] = pk2(s[mi][nj][2], s[mi][nj][3]);
            }

        // ---- GEMM2: O_partial(32x64) += S_slice(32) @ V ----
        #pragma unroll
        for (int ks = 0; ks < 2; ++ks) {
            uint32_t a0[4] = { sp[0][2*ks][0], sp[0][2*ks][1],
                               sp[0][2*ks+1][0], sp[0][2*ks+1][1] };
            uint32_t a1[4] = { sp[1][2*ks][0], sp[1][2*ks][1],
                               sp[1][2*ks+1][0], sp[1][2*ks+1][1] };
            const uint32_t cx = (uint32_t)((((4 * wn + 2 * ks) + csB) ^ l7) << 4);
            #pragma unroll
            for (int njp = 0; njp < 4; ++njp) {
                uint32_t bv[4];
                ldsm4(bv, vbuf + vb_ + (uint32_t)njp * (16 * 128) + cx);
                mma16(o[0][2*njp],   a0, bv);     mma16(o[0][2*njp+1], a0, bv + 2);
                mma16(o[1][2*njp],   a1, bv);     mma16(o[1][2*njp+1], a1, bv + 2);
            }
        }
    }

    // ---- reduce partial O across the 2 wn-warps ----
    float* smf = reinterpret_cast<float*>(sm32);
    __syncthreads();
    #pragma unroll
    for (int w = 0; w < 2; ++w) {
        if (wn == w) {
            #pragma unroll
            for (int mi = 0; mi < 2; ++mi) {
                #pragma unroll
                for (int nj = 0; nj < 8; ++nj) {
                    const int rl = row0 + mi * 16 + g;
                    const int cl = nj * 8 + 2 * tg;
                    float* p0 = smf + rl * OSTR + cl;
                    float* p1 = smf + (rl + 8) * OSTR + cl;
                    if (w == 0) {
                        *(float2*)p0 = make_float2(o[mi][nj][0], o[mi][nj][1]);
                        *(float2*)p1 = make_float2(o[mi][nj][2], o[mi][nj][3]);
                    } else {
                        float2 t0 = *(float2*)p0, t1 = *(float2*)p1;
                        t0.x += o[mi][nj][0]; t0.y += o[mi][nj][1];
                        t1.x += o[mi][nj][2]; t1.y += o[mi][nj][3];
                        *(float2*)p0 = t0;
                        *(float2*)p1 = t1;
                    }
                }
            }
        }
        __syncthreads();
    }

    // ---- LayerNorm over D=64 ----
    if (tid < BM) {
        const float* rowp = smf + tid * OSTR;
        float x[Dd]; float sum = 0.0f;
        #pragma unroll
        for (int c = 0; c < Dd; c += 4) {
            float4 t = *(const float4*)(rowp + c);
            x[c] = t.x; x[c+1] = t.y; x[c+2] = t.z; x[c+3] = t.w;
            sum += t.x + t.y + t.z + t.w;
        }
        const float mean = sum * (1.0f / Dd);
        float var = 0.0f;
        #pragma unroll
        for (int c = 0; c < Dd; ++c) { float d = x[c] - mean; var += d * d; }
        const float inv = rsqrtf(var * (1.0f / Dd) + 1e-12f);
        float* op = out + bho + (size_t)(qt * BM + tid) * Dd;
        #pragma unroll
        for (int c = 0; c < Dd; c += 4) {
            float4 t = make_float4(
                (x[c]   - mean) * inv * __ldg(gamma + c)     + __ldg(beta + c),
                (x[c+1] - mean) * inv * __ldg(gamma + c + 1) + __ldg(beta + c + 1),
                (x[c+2] - mean) * inv * __ldg(gamma + c + 2) + __ldg(beta + c + 2),
                (x[c+3] - mean) * inv * __ldg(gamma + c + 3) + __ldg(beta + c + 3));
            *(float4*)(op + c) = t;
        }
    }
}

extern "C" void kernel_launch(void* const* d_in, const int* in_sizes, int n_in,
                              void* d_out, int out_size)
{
    const float* q     = (const float*)d_in[0];
    const float* k     = (const float*)d_in[1];
    const float* v     = (const float*)d_in[2];
    const int*   mask  = (const int*)  d_in[3];
    const float* gamma = (const float*)d_in[4];
    const float* beta  = (const float*)d_in[5];
    float* out = (float*)d_out;

    const int bh = in_sizes[0] / (Ldim * Dd);   // 24
    const int nk = bh * 256;                    // K-convert blocks
    const int nv = bh * 32;                     // V-transpose blocks
    const int nm = (Ldim * 8 + 7) / 8;          // 2048 mask blocks (8 warps each)

    prelude_k<<<nk + nv + nm, 256>>>(k, v, mask, nk, nv);

    cudaFuncSetAttribute(attn_k, cudaFuncAttributeMaxDynamicSharedMemorySize,
                         SMEMW * (int)sizeof(uint32_t));
    attn_k<<<dim3(Ldim / BM, bh), 256, SMEMW * (int)sizeof(uint32_t)>>>(
        q, gamma, beta, out);
}